// round 11
// baseline (speedup 1.0000x reference)
#include <cuda_runtime.h>
#include <math.h>

#define SS 1024
#define CC 4096
#define KK 4
#define NB 128          // blocks (NB * 8 warps == SS rows); NB <= SM count -> co-resident

// ---------------- scratch (no allocations allowed) ----------------
__device__ float g_P[9 * SS];      // exp(logPi) rows: 0..3 c1, 4..7 c2, 8 root — computed ONCE
__device__ float g_En[SS];         // E_new[s]  (linear)
__device__ float g_ps[NB];         // per-block partial sums
__device__ unsigned int g_barA = 0, g_barB = 0, g_done = 0;  // monotonic tickets (never reset)

__device__ __forceinline__ float softplusf(float x) {
    if (x > 20.0f)  return x;
    if (x < -20.0f) return expf(x);
    return log1pf(expf(x));            // accurate: only 3 uniform scalars
}

// Grid barrier: monotonic counter, replay-safe (no reset), wrap-safe compare.
// All NB blocks are co-resident (NB <= 148 SMs), so spin cannot deadlock.
__device__ __forceinline__ void grid_barrier(unsigned int* bar) {
    __threadfence();                       // release
    __syncthreads();
    if (threadIdx.x == 0) {
        unsigned int t = atomicAdd(bar, 1u);
        unsigned int target = (t / NB + 1u) * NB;
        while ((int)(*(volatile unsigned int*)bar - target) < 0) { }
    }
    __syncthreads();
    __threadfence();                       // acquire
}

__global__ void __launch_bounds__(256) k_fused(
    const float* __restrict__ log_delta,
    const float* __restrict__ log_tau,
    const float* __restrict__ log_lambda,
    const float* __restrict__ E,
    const float* __restrict__ logPi,
    const int*   __restrict__ sC1,
    const int*   __restrict__ sC2,
    const float* __restrict__ recip,
    const int*   __restrict__ splits_c1,
    const int*   __restrict__ splits_c2,
    const float* __restrict__ log_q,
    const void*  __restrict__ is_leaf,
    const int*   __restrict__ rootp,
    float*       __restrict__ out)
{
    __shared__ float sw[9 * SS];   // exp'd rows copied from g_P (36 KB)
    __shared__ float sE[SS];       // E (4 KB)
    __shared__ float s_part[8];
    __shared__ unsigned int s_islast;

    const int tid  = threadIdx.x;
    const int b    = blockIdx.x;
    const int warp = tid >> 5, lane = tid & 31;
    const int s    = b * 8 + warp;

    // ---- issue independent DRAM loads first; they ride across barrier A in regs ----
    const float4* rrow = (const float4*)(recip + (size_t)s * SS);
    float4 rv[8];
    #pragma unroll
    for (int it = 0; it < 8; it++) rv[it] = rrow[lane + it * 32];
    const int i1 = sC1[s], i2 = sC2[s];

    // ---- scalar constants (uniform broadcasts) ----
    const int root = rootp[0];
    const float delta = softplusf(log_delta[0]);
    const float tau   = softplusf(log_tau[0]);
    const float lam   = softplusf(log_lambda[0]);
    const float rs = 1.0f + delta + tau + lam;
    const float pS = 1.0f / rs, pD = delta / rs, pT = tau / rs, pL = lam / rs;

    const unsigned char* lbp = (const unsigned char*)is_leaf;
    const unsigned int*  lwp = (const unsigned int*)is_leaf;
    const bool leaf = (lbp[root] != 0) || (lwp[root] == 0x3F800000u);

    // ---- phase 0: blocks 0..8 exponentiate ONE row each into g_P (exp done once, not 128x) ----
    if (b < 9) {
        int c = (b < 4) ? splits_c1[root * KK + b]
              : (b < 8) ? splits_c2[root * KK + (b - 4)]
                        : root;
        float4 v = ((const float4*)(logPi + (size_t)c * SS))[tid];
        float4 w;
        w.x = __expf(v.x); w.y = __expf(v.y); w.z = __expf(v.z); w.w = __expf(v.w);
        ((float4*)(g_P + b * SS))[tid] = w;
    }

    // ---- grid barrier A: g_P complete ----
    grid_barrier(&g_barA);

    // ---- copy g_P -> smem (pure L2 loads, zero MUFU) + E -> smem ----
    #pragma unroll
    for (int k = 0; k < 9; k++)
        ((float4*)(sw + k * SS))[tid] = ((const float4*)(g_P + k * SS))[tid];
    ((float4*)sE)[tid] = ((const float4*)E)[tid];
    __syncthreads();

    // ---- row dots: warp-per-row, rv already in registers ----
    float acc[10];
    #pragma unroll
    for (int q = 0; q < 10; q++) acc[q] = 0.0f;

    #pragma unroll
    for (int it = 0; it < 8; it++) {
        const int j4 = lane + it * 32;
        const float4 r = rv[it];
        const float4 ev = ((const float4*)sE)[j4];
        acc[0] += r.x + r.y + r.z + r.w;
        acc[1] += r.x * ev.x + r.y * ev.y + r.z * ev.z + r.w * ev.w;
        #pragma unroll
        for (int k = 0; k < 8; k++) {
            const float4 wv = ((const float4*)(sw + k * SS))[j4];
            acc[2 + k] += r.x * wv.x + r.y * wv.y + r.z * wv.z + r.w * wv.w;
        }
    }
    #pragma unroll
    for (int q = 0; q < 10; q++)
        #pragma unroll
        for (int o = 16; o > 0; o >>= 1)
            acc[q] += __shfl_xor_sync(0xffffffffu, acc[q], o);   // totals in ALL lanes

    const float cnt = fmaxf(acc[0], 1.0f);
    const float inv = 1.0f / cnt;

    // ---- local epilogue (pre-barrier B): lanes 0..3 handle k; all data in smem/regs ----
    float lin_local = 0.0f;
    if (!leaf) {
        if (lane < 4) {
            const int k = lane;
            const float q = __expf(log_q[root * KK + k]);
            const float* PA = sw + k * SS;
            const float* PB = sw + (4 + k) * SS;
            float A  = PA[s],  B  = PB[s];
            float Af = PA[i1], Ag = PA[i2];
            float Bf = PB[i1], Bg = PB[i2];
            float sA = acc[2 + k];
            float sB = acc[6 + k];
            lin_local = q * (pS * (Af * Bg + Ag * Bf)
                           + pD * (A * B)
                           + (pT * inv) * (A * sB + B * sA));
        }
        lin_local += __shfl_xor_sync(0xffffffffu, lin_local, 1);
        lin_local += __shfl_xor_sync(0xffffffffu, lin_local, 2);  // k-sum lands on lane 0
    }

    // ---- publish E_new[s] (only cross-block value) ----
    if (lane == 0) {
        float Ebar = acc[1] * inv;
        float Es = sE[s];
        float Enew = pL + pD * Es * Es + pT * Es * Ebar + pS * sE[i1] * sE[i2];
        g_En[s] = Enew;
    }

    // ---- grid barrier B: all g_En visible ----
    grid_barrier(&g_barB);

    // ---- sl term + per-block sum ----
    if (lane == 0) {
        float lin;
        if (leaf) {
            lin = sw[8 * SS + s];
        } else {
            float sl = sw[8 * SS + i1] * g_En[i2] + sw[8 * SS + i2] * g_En[i1];
            lin = lin_local + pS * sl;
        }
        s_part[warp] = lin;
    }
    __syncthreads();
    if (tid == 0) {
        float t = 0.0f;
        #pragma unroll
        for (int w2 = 0; w2 < 8; w2++) t += s_part[w2];
        g_ps[b] = t;
        __threadfence();
        unsigned int prev = atomicAdd(&g_done, 1u);
        s_islast = ((prev % NB) == (unsigned int)(NB - 1)) ? 1u : 0u;
    }
    __syncthreads();
    if (!s_islast) return;
    __threadfence();   // acquire: all partials visible

    // ---- last block: fixed-order deterministic final sum + one log ----
    if (warp == 0) {
        float v = g_ps[lane] + g_ps[lane + 32] + g_ps[lane + 64] + g_ps[lane + 96];
        #pragma unroll
        for (int o = 16; o > 0; o >>= 1)
            v += __shfl_xor_sync(0xffffffffu, v, o);
        if (lane == 0) out[0] = logf(v);
    }
}

// ---------------- launch ----------------
extern "C" void kernel_launch(void* const* d_in, const int* in_sizes, int n_in,
                              void* d_out, int out_size)
{
    const float* log_delta  = (const float*)d_in[0];
    const float* log_tau    = (const float*)d_in[1];
    const float* log_lambda = (const float*)d_in[2];
    const float* E          = (const float*)d_in[3];
    const float* log_Pi     = (const float*)d_in[4];
    const int*   s_C1       = (const int*)  d_in[5];
    const int*   s_C2       = (const int*)  d_in[6];
    const float* recip      = (const float*)d_in[7];
    const int*   splits_c1  = (const int*)  d_in[8];
    const int*   splits_c2  = (const int*)  d_in[9];
    const float* log_q      = (const float*)d_in[10];
    const void*  is_leaf    = (const void*) d_in[11];
    const int*   root_id    = (const int*)  d_in[12];
    float* out = (float*)d_out;

    k_fused<<<NB, 256>>>(log_delta, log_tau, log_lambda, E, log_Pi,
                         s_C1, s_C2, recip, splits_c1, splits_c2,
                         log_q, is_leaf, root_id, out);
}

// round 12
// speedup vs baseline: 1.0173x; 1.0173x over previous
#include <cuda_runtime.h>
#include <math.h>

#define SS 1024
#define CC 4096
#define KK 4
#define NB 64           // blocks (NB * 16 warps == SS rows); co-resident
#define NT 512          // threads per block (16 warps)

// ---------------- scratch (no allocations allowed) ----------------
__device__ float g_En[SS];         // E_new[s] (linear) — the ONLY cross-block array
__device__ float g_ps[NB];         // per-block partial sums
__device__ unsigned int g_bar = 0, g_done = 0;   // monotonic tickets (never reset)

__device__ __forceinline__ float softplusf(float x) {
    if (x > 20.0f)  return x;
    if (x < -20.0f) return expf(x);
    return log1pf(expf(x));            // accurate: only 3 uniform scalars
}

// Grid barrier: monotonic counter, replay-safe (no reset), wrap-safe compare.
// All NB blocks are co-resident (NB <= 148 SMs), so spin cannot deadlock.
__device__ __forceinline__ void grid_barrier(unsigned int* bar) {
    __threadfence();                       // release
    __syncthreads();
    if (threadIdx.x == 0) {
        unsigned int t = atomicAdd(bar, 1u);
        unsigned int target = (t / NB + 1u) * NB;
        while ((int)(*(volatile unsigned int*)bar - target) < 0) { }
    }
    __syncthreads();
    __threadfence();                       // acquire
}

__global__ void __launch_bounds__(NT) k_fused(
    const float* __restrict__ log_delta,
    const float* __restrict__ log_tau,
    const float* __restrict__ log_lambda,
    const float* __restrict__ E,
    const float* __restrict__ logPi,
    const int*   __restrict__ sC1,
    const int*   __restrict__ sC2,
    const float* __restrict__ recip,
    const int*   __restrict__ splits_c1,
    const int*   __restrict__ splits_c2,
    const float* __restrict__ log_q,
    const void*  __restrict__ is_leaf,
    const int*   __restrict__ rootp,
    float*       __restrict__ out)
{
    __shared__ float sw[9 * SS];   // exp'd rows: 0..3 c1, 4..7 c2, 8 root (36 KB)
    __shared__ float sE[SS];       // E (4 KB)
    __shared__ float s_part[16];
    __shared__ unsigned int s_islast;

    const int tid  = threadIdx.x;
    const int b    = blockIdx.x;
    const int warp = tid >> 5, lane = tid & 31;
    const int s    = b * 16 + warp;          // warp-per-row

    // ---- issue independent loads first (L2-resident across replays) ----
    const float4* rrow = (const float4*)(recip + (size_t)s * SS);
    float4 rv[8];
    #pragma unroll
    for (int it = 0; it < 8; it++) rv[it] = rrow[lane + it * 32];
    const int i1 = sC1[s], i2 = sC2[s];

    // ---- scalar constants (uniform broadcasts) ----
    const int root = rootp[0];
    const float delta = softplusf(log_delta[0]);
    const float tau   = softplusf(log_tau[0]);
    const float lam   = softplusf(log_lambda[0]);
    const float rs = 1.0f + delta + tau + lam;
    const float pS = 1.0f / rs, pD = delta / rs, pT = tau / rs, pL = lam / rs;

    const unsigned char* lbp = (const unsigned char*)is_leaf;
    const unsigned int*  lwp = (const unsigned int*)is_leaf;
    const bool leaf = (lbp[root] != 0) || (lwp[root] == 0x3F800000u);

    // ---- stage 9 exp'd rows + E in shared (512 threads: 2 rows per pass) ----
    {
        const int half = tid >> 8;         // 0 or 1
        const int f4   = tid & 255;        // float4 index within a row
        #pragma unroll
        for (int kk = 0; kk < 4; kk++) {
            const int k = kk * 2 + half;   // rows 0..7
            int c = (k < 4) ? splits_c1[root * KK + k] : splits_c2[root * KK + (k - 4)];
            float4 v = ((const float4*)(logPi + (size_t)c * SS))[f4];
            float4 w;
            w.x = __expf(v.x); w.y = __expf(v.y); w.z = __expf(v.z); w.w = __expf(v.w);
            ((float4*)(sw + k * SS))[f4] = w;
        }
        if (half == 0) {                   // row 8 = root
            float4 v = ((const float4*)(logPi + (size_t)root * SS))[f4];
            float4 w;
            w.x = __expf(v.x); w.y = __expf(v.y); w.z = __expf(v.z); w.w = __expf(v.w);
            ((float4*)(sw + 8 * SS))[f4] = w;
        } else {                           // E
            ((float4*)sE)[f4] = ((const float4*)E)[f4];
        }
    }
    __syncthreads();

    // ---- row dots: rv already in registers ----
    float acc[10];
    #pragma unroll
    for (int q = 0; q < 10; q++) acc[q] = 0.0f;

    #pragma unroll
    for (int it = 0; it < 8; it++) {
        const int j4 = lane + it * 32;
        const float4 r = rv[it];
        const float4 ev = ((const float4*)sE)[j4];
        acc[0] += r.x + r.y + r.z + r.w;
        acc[1] += r.x * ev.x + r.y * ev.y + r.z * ev.z + r.w * ev.w;
        #pragma unroll
        for (int k = 0; k < 8; k++) {
            const float4 wv = ((const float4*)(sw + k * SS))[j4];
            acc[2 + k] += r.x * wv.x + r.y * wv.y + r.z * wv.z + r.w * wv.w;
        }
    }
    #pragma unroll
    for (int q = 0; q < 10; q++)
        #pragma unroll
        for (int o = 16; o > 0; o >>= 1)
            acc[q] += __shfl_xor_sync(0xffffffffu, acc[q], o);   // totals in ALL lanes

    const float cnt = fmaxf(acc[0], 1.0f);
    const float inv = 1.0f / cnt;

    // ---- local epilogue (pre-barrier): lanes 0..3 handle k ----
    float lin_local = 0.0f;
    if (!leaf) {
        if (lane < 4) {
            const int k = lane;
            const float q = __expf(log_q[root * KK + k]);
            const float* PA = sw + k * SS;
            const float* PB = sw + (4 + k) * SS;
            float A  = PA[s],  B  = PB[s];
            float Af = PA[i1], Ag = PA[i2];
            float Bf = PB[i1], Bg = PB[i2];
            float sA = acc[2 + k];
            float sB = acc[6 + k];
            lin_local = q * (pS * (Af * Bg + Ag * Bf)
                           + pD * (A * B)
                           + (pT * inv) * (A * sB + B * sA));
        }
        lin_local += __shfl_xor_sync(0xffffffffu, lin_local, 1);
        lin_local += __shfl_xor_sync(0xffffffffu, lin_local, 2);  // k-sum on lane 0
    }

    // ---- publish E_new[s] ----
    if (lane == 0) {
        float Ebar = acc[1] * inv;
        float Es = sE[s];
        float Enew = pL + pD * Es * Es + pT * Es * Ebar + pS * sE[i1] * sE[i2];
        g_En[s] = Enew;
    }

    // ---- ONE grid barrier: all g_En visible ----
    grid_barrier(&g_bar);

    // ---- sl term + per-block sum ----
    if (lane == 0) {
        float lin;
        if (leaf) {
            lin = sw[8 * SS + s];
        } else {
            float sl = sw[8 * SS + i1] * g_En[i2] + sw[8 * SS + i2] * g_En[i1];
            lin = lin_local + pS * sl;
        }
        s_part[warp] = lin;
    }
    __syncthreads();
    if (tid == 0) {
        float t = 0.0f;
        #pragma unroll
        for (int w2 = 0; w2 < 16; w2++) t += s_part[w2];
        g_ps[b] = t;
        __threadfence();
        unsigned int prev = atomicAdd(&g_done, 1u);
        s_islast = ((prev % NB) == (unsigned int)(NB - 1)) ? 1u : 0u;
    }
    __syncthreads();
    if (!s_islast) return;
    __threadfence();   // acquire: all partials visible

    // ---- last block: fixed-order deterministic final sum + one log ----
    if (warp == 0) {
        float v = g_ps[lane] + g_ps[lane + 32];
        #pragma unroll
        for (int o = 16; o > 0; o >>= 1)
            v += __shfl_xor_sync(0xffffffffu, v, o);
        if (lane == 0) out[0] = logf(v);
    }
}

// ---------------- launch ----------------
extern "C" void kernel_launch(void* const* d_in, const int* in_sizes, int n_in,
                              void* d_out, int out_size)
{
    const float* log_delta  = (const float*)d_in[0];
    const float* log_tau    = (const float*)d_in[1];
    const float* log_lambda = (const float*)d_in[2];
    const float* E          = (const float*)d_in[3];
    const float* log_Pi     = (const float*)d_in[4];
    const int*   s_C1       = (const int*)  d_in[5];
    const int*   s_C2       = (const int*)  d_in[6];
    const float* recip      = (const float*)d_in[7];
    const int*   splits_c1  = (const int*)  d_in[8];
    const int*   splits_c2  = (const int*)  d_in[9];
    const float* log_q      = (const float*)d_in[10];
    const void*  is_leaf    = (const void*) d_in[11];
    const int*   root_id    = (const int*)  d_in[12];
    float* out = (float*)d_out;

    k_fused<<<NB, NT>>>(log_delta, log_tau, log_lambda, E, log_Pi,
                        s_C1, s_C2, recip, splits_c1, splits_c2,
                        log_q, is_leaf, root_id, out);
}

// round 13
// speedup vs baseline: 1.1775x; 1.1575x over previous
#include <cuda_runtime.h>
#include <math.h>

#define SS 1024
#define CC 4096
#define KK 4
#define NB 128          // blocks (NB * 8 warps == SS rows)

// ---------------- scratch (no allocations allowed) ----------------
__device__ float g_ps[NB];                 // per-block partial sums
__device__ unsigned int g_done = 0;        // monotonic ticket (never reset)

__device__ __forceinline__ float softplusf(float x) {
    if (x > 20.0f)  return x;
    if (x < -20.0f) return expf(x);
    return log1pf(expf(x));            // accurate: only 3 uniform scalars
}

__global__ void __launch_bounds__(256) k_fused(
    const float* __restrict__ log_delta,
    const float* __restrict__ log_tau,
    const float* __restrict__ log_lambda,
    const float* __restrict__ E,
    const float* __restrict__ logPi,
    const int*   __restrict__ sC1,
    const int*   __restrict__ sC2,
    const float* __restrict__ recip,
    const int*   __restrict__ splits_c1,
    const int*   __restrict__ splits_c2,
    const float* __restrict__ log_q,
    const void*  __restrict__ is_leaf,
    const int*   __restrict__ rootp,
    float*       __restrict__ out)
{
    __shared__ float sw[9 * SS];   // exp'd rows: 0..3 c1, 4..7 c2, 8 root (36 KB)
    __shared__ float sE[SS];       // E (4 KB)
    __shared__ float s_part[8];
    __shared__ unsigned int s_islast;

    const int tid  = threadIdx.x;
    const int b    = blockIdx.x;
    const int warp = tid >> 5, lane = tid & 31;
    const int s    = b * 8 + warp;

    // ---- issue independent loads early ----
    const int i1 = sC1[s], i2 = sC2[s];
    const float4* rrow = (const float4*)(recip + (size_t)s * SS);
    float4 rv[8];
    #pragma unroll
    for (int it = 0; it < 8; it++) rv[it] = rrow[lane + it * 32];
    // second-level index gathers (needed for local E_new recomputation)
    const int i1a = sC1[i1], i1b = sC2[i1];
    const int i2a = sC1[i2], i2b = sC2[i2];

    // ---- scalar constants (uniform broadcasts) ----
    const int root = rootp[0];
    const float delta = softplusf(log_delta[0]);
    const float tau   = softplusf(log_tau[0]);
    const float lam   = softplusf(log_lambda[0]);
    const float rs = 1.0f + delta + tau + lam;
    const float pS = 1.0f / rs, pD = delta / rs, pT = tau / rs, pL = lam / rs;

    const unsigned char* lbp = (const unsigned char*)is_leaf;
    const unsigned int*  lwp = (const unsigned int*)is_leaf;
    const bool leaf = (lbp[root] != 0) || (lwp[root] == 0x3F800000u);

    // ---- stage 9 exp'd rows + E in shared (redundant per block — proven cheap) ----
    #pragma unroll
    for (int k = 0; k < 9; k++) {
        int c = (k < 4) ? splits_c1[root * KK + k]
              : (k < 8) ? splits_c2[root * KK + (k - 4)]
                        : root;
        float4 v = ((const float4*)(logPi + (size_t)c * SS))[tid];
        float4 w;
        w.x = __expf(v.x); w.y = __expf(v.y); w.z = __expf(v.z); w.w = __expf(v.w);
        ((float4*)(sw + k * SS))[tid] = w;
    }
    ((float4*)sE)[tid] = ((const float4*)E)[tid];
    __syncthreads();

    // ---- dots: row s (10 accs) + rows i1, i2 (4 accs) ----
    float acc[14];
    #pragma unroll
    for (int q = 0; q < 14; q++) acc[q] = 0.0f;

    #pragma unroll
    for (int it = 0; it < 8; it++) {
        const int j4 = lane + it * 32;
        const float4 r = rv[it];
        const float4 ev = ((const float4*)sE)[j4];
        acc[0] += r.x + r.y + r.z + r.w;
        acc[1] += r.x * ev.x + r.y * ev.y + r.z * ev.z + r.w * ev.w;
        #pragma unroll
        for (int k = 0; k < 8; k++) {
            const float4 wv = ((const float4*)(sw + k * SS))[j4];
            acc[2 + k] += r.x * wv.x + r.y * wv.y + r.z * wv.z + r.w * wv.w;
        }
    }
    // rows i1, i2: only cnt + E-dot needed
    {
        const float4* r1 = (const float4*)(recip + (size_t)i1 * SS);
        const float4* r2 = (const float4*)(recip + (size_t)i2 * SS);
        #pragma unroll
        for (int it = 0; it < 8; it++) {
            const int j4 = lane + it * 32;
            const float4 a = r1[j4];
            const float4 c = r2[j4];
            const float4 ev = ((const float4*)sE)[j4];
            acc[10] += a.x + a.y + a.z + a.w;
            acc[11] += a.x * ev.x + a.y * ev.y + a.z * ev.z + a.w * ev.w;
            acc[12] += c.x + c.y + c.z + c.w;
            acc[13] += c.x * ev.x + c.y * ev.y + c.z * ev.z + c.w * ev.w;
        }
    }

    #pragma unroll
    for (int q = 0; q < 14; q++)
        #pragma unroll
        for (int o = 16; o > 0; o >>= 1)
            acc[q] += __shfl_xor_sync(0xffffffffu, acc[q], o);   // totals in ALL lanes

    const float inv = 1.0f / fmaxf(acc[0], 1.0f);

    // ---- fully local epilogue: lanes 0..3 handle k ----
    float lin_local = 0.0f;
    if (!leaf) {
        if (lane < 4) {
            const int k = lane;
            const float q = __expf(log_q[root * KK + k]);
            const float* PA = sw + k * SS;
            const float* PB = sw + (4 + k) * SS;
            float A  = PA[s],  B  = PB[s];
            float Af = PA[i1], Ag = PA[i2];
            float Bf = PB[i1], Bg = PB[i2];
            float sA = acc[2 + k];
            float sB = acc[6 + k];
            lin_local = q * (pS * (Af * Bg + Ag * Bf)
                           + pD * (A * B)
                           + (pT * inv) * (A * sB + B * sA));
        }
        lin_local += __shfl_xor_sync(0xffffffffu, lin_local, 1);
        lin_local += __shfl_xor_sync(0xffffffffu, lin_local, 2);  // k-sum lands on lane 0
    }

    // ---- sl term with LOCALLY recomputed E_new[i1], E_new[i2] (no barrier needed) ----
    if (lane == 0) {
        float lin;
        if (leaf) {
            lin = sw[8 * SS + s];
        } else {
            float inv1 = 1.0f / fmaxf(acc[10], 1.0f);
            float inv2 = 1.0f / fmaxf(acc[12], 1.0f);
            float E1 = sE[i1], E2 = sE[i2];
            float En1 = pL + pD * E1 * E1 + pT * E1 * (acc[11] * inv1) + pS * sE[i1a] * sE[i1b];
            float En2 = pL + pD * E2 * E2 + pT * E2 * (acc[13] * inv2) + pS * sE[i2a] * sE[i2b];
            float sl = sw[8 * SS + i1] * En2 + sw[8 * SS + i2] * En1;
            lin = lin_local + pS * sl;
        }
        s_part[warp] = lin;
    }
    __syncthreads();
    if (tid == 0) {
        float t = 0.0f;
        #pragma unroll
        for (int w2 = 0; w2 < 8; w2++) t += s_part[w2];
        g_ps[b] = t;
        __threadfence();                       // release partial
        unsigned int prev = atomicAdd(&g_done, 1u);
        s_islast = ((prev % NB) == (unsigned int)(NB - 1)) ? 1u : 0u;
    }
    __syncthreads();
    if (!s_islast) return;
    __threadfence();                           // acquire: all partials visible

    // ---- last block: fixed-order deterministic final sum + one log ----
    if (warp == 0) {
        float v = g_ps[lane] + g_ps[lane + 32] + g_ps[lane + 64] + g_ps[lane + 96];
        #pragma unroll
        for (int o = 16; o > 0; o >>= 1)
            v += __shfl_xor_sync(0xffffffffu, v, o);
        if (lane == 0) out[0] = logf(v);
    }
}

// ---------------- launch ----------------
extern "C" void kernel_launch(void* const* d_in, const int* in_sizes, int n_in,
                              void* d_out, int out_size)
{
    const float* log_delta  = (const float*)d_in[0];
    const float* log_tau    = (const float*)d_in[1];
    const float* log_lambda = (const float*)d_in[2];
    const float* E          = (const float*)d_in[3];
    const float* log_Pi     = (const float*)d_in[4];
    const int*   s_C1       = (const int*)  d_in[5];
    const int*   s_C2       = (const int*)  d_in[6];
    const float* recip      = (const float*)d_in[7];
    const int*   splits_c1  = (const int*)  d_in[8];
    const int*   splits_c2  = (const int*)  d_in[9];
    const float* log_q      = (const float*)d_in[10];
    const void*  is_leaf    = (const void*) d_in[11];
    const int*   root_id    = (const int*)  d_in[12];
    float* out = (float*)d_out;

    k_fused<<<NB, 256>>>(log_delta, log_tau, log_lambda, E, log_Pi,
                         s_C1, s_C2, recip, splits_c1, splits_c2,
                         log_q, is_leaf, root_id, out);
}